// round 17
// baseline (speedup 1.0000x reference)
#include <cuda_runtime.h>
#include <stdint.h>

// FINAL — best measured configuration (R15: 4.96us kernel, occ 63%, issue 14%).
//
// Problem: speculative-decode input prep. Inputs int32 (harness maps the int64
// JAX reference inputs to int32; verified by the R6 diagnostic dump), in
// setup_inputs dict order. Output float32, layout [tok | pos | len | slot],
// each R*T = 65536 elements.
//
// Shape rationale (measured across R8-R16): maximally thin threads win. One
// thread per output element (262144 threads, 1024 CTAs x 256). The output
// segment (idx>>16) is uniform per CTA -> divergence-free specialization:
//   seg 0 (tok):  j>0 -> 1 spec load (depth-1, independent of accepted_num);
//                 j==0 -> accepted -> sampled (depth-2, 1/8 of lanes)
//   seg 1 (pos):  2 parallel broadcast loads + arithmetic
//   seg 2 (len):  same as pos
//   seg 3 (slot): accepted/in_pos -> block_table gather (critical path)
// Every thread issues exactly one coalesced 4B store. Kernel is at the
// launch+ramp floor: all pipes <5% busy; 4.96us never beaten from any shape.
constexpr int R    = 8192;
constexpr int SPEC = 7;
constexpr int T    = 1 + SPEC;   // 8
constexpr int SC   = SPEC + 1;   // 8
constexpr int MAX_BLOCKS = 2048;
constexpr int RT   = R * T;      // 65536
// BLOCK_SIZE = 128 -> shift 7, mask 127

__global__ __launch_bounds__(256) void prep_inputs_kernel(
    const int* __restrict__ sampled,      // [R, SC]        d_in[1]
    const int* __restrict__ in_pos,       // [R*T]          d_in[2]
    const int* __restrict__ block_table,  // [R, MAX_BLOCKS] d_in[5]
    const int* __restrict__ spec,         // [R, SPEC]      d_in[6]
    const int* __restrict__ accepted,     // [R]            d_in[7]
    float* __restrict__ out)              // [4 * RT] float32
{
    int idx = blockIdx.x * blockDim.x + threadIdx.x;   // 0 .. 4*RT-1
    int seg = idx >> 16;     // output segment, uniform per CTA
    int e   = idx & (RT - 1);
    int r   = e >> 3;        // request
    int j   = e & 7;         // token within request

    float v;
    if (seg == 0) {
        if (j != 0) {
            v = (float)spec[r * SPEC + (j - 1)];           // depth-1
        } else {
            int a = accepted[r];
            a = a < 1 ? 1 : (a > SC ? SC : a);
            v = (float)sampled[r * SC + (a - 1)];          // depth-2, 1/8 lanes
        }
    } else {
        int a  = accepted[r];                              // parallel broadcast
        int pb = in_pos[r * T];                            // parallel broadcast
        a = a < 1 ? 1 : (a > SC ? SC : a);
        int p = pb + a + j;
        if (seg == 1) {
            v = (float)p;
        } else if (seg == 2) {
            v = (float)(p + 1);
        } else {
            int bl = block_table[r * MAX_BLOCKS + (p >> 7)];
            v = (float)((bl << 7) | (p & 127));   // slots < 2^27: exact in int32
        }
    }

    out[idx] = v;   // consecutive idx -> perfectly coalesced
}

extern "C" void kernel_launch(void* const* d_in, const int* in_sizes, int n_in,
                              void* d_out, int out_size)
{
    // dict order (verified R6): 0 input_tokens, 1 sampled_tokens, 2 input_positions,
    // 3 seq_lens, 4 slot_mapping, 5 block_table, 6 spec_tokens, 7 accepted_num,
    // 8 num_seqs, 9 num_queries, 10 block_size
    const int* sampled  = (const int*)d_in[1];
    const int* in_pos   = (const int*)d_in[2];
    const int* bt       = (const int*)d_in[5];
    const int* spec     = (const int*)d_in[6];
    const int* accepted = (const int*)d_in[7];
    float* out = (float*)d_out;

    (void)in_sizes; (void)n_in; (void)out_size;

    int threads = 256;
    int blocks = (4 * RT) / threads;   // 1024 CTAs x 256 threads
    prep_inputs_kernel<<<blocks, threads>>>(sampled, in_pos, bt, spec, accepted, out);
}